// round 6
// baseline (speedup 1.0000x reference)
#include <cuda_runtime.h>
#include <cuda_bf16.h>
#include <cstdint>

// Grouped GEMM C[e] = A[e] @ B[e]^T via tcgen05 bf16-split (3-MMA fp32 emulation).
// E=32, M=1024, K=512, N=512 fp32. Rows m >= expert_num_tokens[e] -> 0.
//
// R6: TS-mode MMA (A operand in TMEM). Warps 0-3 LDG A fp32 -> hi/lo bf16 split
// -> tcgen05.st into TMEM (2-stage). B (pre-split scratch) via cp.async into a
// 3-stage SMEM pipeline (2 periods of latency slack). One bar per chunk.
// tcgen05 guarded for the portable compute_103 PTX pass.

#define E_ 32
#define M_ 1024
#define K_ 512
#define N_ 512

#define BM 128
#define BN 256
#define BK 64            // k-elems per chunk (128B bf16 rows -> SW128)
#define NCHUNK (K_/BK)   // 8
#define NTHR 256

#if defined(__CUDA_ARCH__) && !defined(__CUDA_ARCH_FEAT_SM103_ALL) && !defined(__CUDA_ARCH_FEAT_SM100_ALL)
#define TC_FALLBACK 1
#else
#define TC_FALLBACK 0
#endif

// ---- scratch: bf16 hi/lo split of B only ----
__device__ __align__(16) __nv_bfloat16 g_Bh[E_*N_*K_];
__device__ __align__(16) __nv_bfloat16 g_Bl[E_*N_*K_];

// ======================= portable PTX helpers =======================
__device__ __forceinline__ uint32_t smem_u32(const void* p) {
    uint32_t a;
    asm("{ .reg .u64 t; cvta.to.shared.u64 t, %1; cvt.u32.u64 %0, t; }" : "=r"(a) : "l"(p));
    return a;
}
__device__ __forceinline__ uint32_t elect_one() {
    uint32_t pred;
    asm volatile("{ .reg .pred p; elect.sync _|p, 0xFFFFFFFF; selp.b32 %0, 1, 0, p; }" : "=r"(pred));
    return pred;
}
#define MBAR_INIT(addr, cnt) \
    asm volatile("mbarrier.init.shared.b64 [%0], %1;" :: "r"(addr), "r"(cnt) : "memory")
#define MBAR_INVAL(addr) \
    asm volatile("mbarrier.inval.shared.b64 [%0];" :: "r"(addr) : "memory")

__device__ __forceinline__ void mbar_wait(uint32_t mbar, uint32_t parity) {
    uint32_t done;
    asm volatile("{ .reg .pred p; mbarrier.try_wait.parity.acquire.cta.shared::cta.b64 p, [%1], %2; selp.b32 %0,1,0,p; }"
                 : "=r"(done) : "r"(mbar), "r"(parity) : "memory");
    if (!done) {
        asm volatile("{ .reg .pred P1;\n"
                     "WL_%=: mbarrier.try_wait.parity.acquire.cta.shared::cta.b64 P1, [%0], %1, 0x989680;\n"
                     "@P1 bra.uni WD_%=;\n bra.uni WL_%=;\n WD_%=: }"
                     :: "r"(mbar), "r"(parity) : "memory");
    }
}

__device__ __forceinline__ void cp16(uint32_t s, const void* g) {
    asm volatile("cp.async.cg.shared.global [%0], [%1], 16;" :: "r"(s), "l"(g));
}
#define CP_COMMIT() asm volatile("cp.async.commit_group;" ::: "memory")
#define CP_WAIT0()  asm volatile("cp.async.wait_group 0;" ::: "memory")
#define CP_WAIT1()  asm volatile("cp.async.wait_group 1;" ::: "memory")
#define CP_WAIT2()  asm volatile("cp.async.wait_group 2;" ::: "memory")
#define FENCE_ASYNC() asm volatile("fence.proxy.async.shared::cta;" ::: "memory")

// ======================= tcgen05 helpers (sm_103a pass only) =======================
#if !TC_FALLBACK
#define TC_ALLOC(smem_addr, ncols) \
    asm volatile("tcgen05.alloc.cta_group::1.sync.aligned.shared::cta.b32 [%0], %1;" \
                 :: "r"(smem_addr), "r"(ncols) : "memory")
#define TC_DEALLOC(tmem, ncols) \
    asm volatile("tcgen05.dealloc.cta_group::1.sync.aligned.b32 %0, %1;" :: "r"(tmem), "r"(ncols))
#define TC_RELINQ() \
    asm volatile("tcgen05.relinquish_alloc_permit.cta_group::1.sync.aligned;")
#define TC_COMMIT(mbar) \
    asm volatile("tcgen05.commit.cta_group::1.mbarrier::arrive::one.shared::cluster.b64 [%0];" \
                 :: "r"(mbar) : "memory")
#define TC_FENCE_BEFORE() asm volatile("tcgen05.fence::before_thread_sync;" ::: "memory")
#define TC_FENCE_AFTER()  asm volatile("tcgen05.fence::after_thread_sync;" ::: "memory")
#define TC_WAIT_LD()      asm volatile("tcgen05.wait::ld.sync.aligned;" ::: "memory")
#define TC_WAIT_ST()      asm volatile("tcgen05.wait::st.sync.aligned;" ::: "memory")

// TS-form MMA: A in TMEM, B in SMEM
__device__ __forceinline__ void mma_f16_ts(uint32_t d, uint32_t a, uint64_t bd,
                                           uint32_t idesc, uint32_t enable) {
    asm volatile("{ .reg .pred p; setp.ne.u32 p, %5, 0;\n"
                 "tcgen05.mma.cta_group::1.kind::f16 [%0], [%1], %2, %3, {%4,%4,%4,%4}, p; }"
                 :: "r"(d), "r"(a), "l"(bd), "r"(idesc), "r"(0u), "r"(enable) : "memory");
}

#define LDTM_X32(r, addr) \
    asm volatile("tcgen05.ld.sync.aligned.32x32b.x32.b32 " \
        "{%0,%1,%2,%3,%4,%5,%6,%7,%8,%9,%10,%11,%12,%13,%14,%15," \
        "%16,%17,%18,%19,%20,%21,%22,%23,%24,%25,%26,%27,%28,%29,%30,%31}, [%32];" \
        : "=r"((r)[0]),"=r"((r)[1]),"=r"((r)[2]),"=r"((r)[3]),"=r"((r)[4]),"=r"((r)[5]),"=r"((r)[6]),"=r"((r)[7]), \
          "=r"((r)[8]),"=r"((r)[9]),"=r"((r)[10]),"=r"((r)[11]),"=r"((r)[12]),"=r"((r)[13]),"=r"((r)[14]),"=r"((r)[15]), \
          "=r"((r)[16]),"=r"((r)[17]),"=r"((r)[18]),"=r"((r)[19]),"=r"((r)[20]),"=r"((r)[21]),"=r"((r)[22]),"=r"((r)[23]), \
          "=r"((r)[24]),"=r"((r)[25]),"=r"((r)[26]),"=r"((r)[27]),"=r"((r)[28]),"=r"((r)[29]),"=r"((r)[30]),"=r"((r)[31]) \
        : "r"(addr))

#define STTM_X32(addr, r) \
    asm volatile("tcgen05.st.sync.aligned.32x32b.x32.b32 [%0], " \
        "{%1,%2,%3,%4,%5,%6,%7,%8,%9,%10,%11,%12,%13,%14,%15,%16," \
        "%17,%18,%19,%20,%21,%22,%23,%24,%25,%26,%27,%28,%29,%30,%31,%32};" \
        :: "r"(addr), \
           "r"((r)[0]),"r"((r)[1]),"r"((r)[2]),"r"((r)[3]),"r"((r)[4]),"r"((r)[5]),"r"((r)[6]),"r"((r)[7]), \
           "r"((r)[8]),"r"((r)[9]),"r"((r)[10]),"r"((r)[11]),"r"((r)[12]),"r"((r)[13]),"r"((r)[14]),"r"((r)[15]), \
           "r"((r)[16]),"r"((r)[17]),"r"((r)[18]),"r"((r)[19]),"r"((r)[20]),"r"((r)[21]),"r"((r)[22]),"r"((r)[23]), \
           "r"((r)[24]),"r"((r)[25]),"r"((r)[26]),"r"((r)[27]),"r"((r)[28]),"r"((r)[29]),"r"((r)[30]),"r"((r)[31]) \
        : "memory")
#endif // !TC_FALLBACK

// SW128 K-major descriptor (layout=2, version=1, SBO=64, LBO=1)
static constexpr uint64_t DESC_SW128 =
    (2ull << 61) | (1ull << 46) | (64ull << 32) | (1ull << 16);
__device__ __forceinline__ uint64_t sdesc(uint32_t a) {
    return DESC_SW128 | ((uint64_t)(a >> 4) & 0x3FFF);
}

// idesc: F32 accum, BF16 x BF16, M=128, N=256, K-major B
static constexpr uint32_t IDESC =
    (1u << 4) | (1u << 7) | (1u << 10) | ((BN / 8) << 17) | ((BM / 16) << 24);

// ======================= B conversion prepass =======================
__global__ void __launch_bounds__(256) convertB(const float* __restrict__ B) {
    const uint32_t nvec = (uint32_t)(E_ * N_ * K_ / 4);
    const uint32_t stride = gridDim.x * blockDim.x;
    for (uint32_t i = blockIdx.x * blockDim.x + threadIdx.x; i < nvec; i += stride) {
        const uint32_t elem = i * 4;
        const float4 v = *reinterpret_cast<const float4*>(B + elem);
        __nv_bfloat162 h01 = __float22bfloat162_rn(make_float2(v.x, v.y));
        __nv_bfloat162 h23 = __float22bfloat162_rn(make_float2(v.z, v.w));
        float2 f01 = __bfloat1622float2(h01);
        float2 f23 = __bfloat1622float2(h23);
        __nv_bfloat162 l01 = __float22bfloat162_rn(make_float2(v.x - f01.x, v.y - f01.y));
        __nv_bfloat162 l23 = __float22bfloat162_rn(make_float2(v.z - f23.x, v.w - f23.y));
        uint2 hu, lu;
        hu.x = reinterpret_cast<uint32_t&>(h01); hu.y = reinterpret_cast<uint32_t&>(h23);
        lu.x = reinterpret_cast<uint32_t&>(l01); lu.y = reinterpret_cast<uint32_t&>(l23);
        *reinterpret_cast<uint2*>(&g_Bh[elem]) = hu;
        *reinterpret_cast<uint2*>(&g_Bl[elem]) = lu;
    }
}

// ======================= fused GEMM =======================
// SMEM: [0] tmem ptr; [16],[24] mbarriers; B stages at 1024 + s*65536
//   each stage: Bh 32KB (256 rows x 128B, SW128) then Bl 32KB.
// TMEM (512 cols): D @ 0..255; A[buf] @ 256 + buf*64 (hi +0, lo +32).
#define SM_TMEM 0
#define SM_MBAR0 16
#define SM_MBAR1 24
#define OFF_B   1024
#define B_STAGE 65536
#define SMEM_TOTAL (1024 + 3 * B_STAGE)
#define TMEM_COLS 512
#define TM_A_OFF 256

#if !TC_FALLBACK
// warps 0-3 (tid<128): LDG one chunk of A (thread = row, 16 float4 = cols 0..63)
__device__ __forceinline__ void loadA_regs(float4 (&r)[16], const float* __restrict__ Ab,
                                           int c, int row) {
    const float* Ar = Ab + (size_t)row * K_ + c * BK;
    #pragma unroll
    for (int j = 0; j < 16; j++)
        r[j] = *reinterpret_cast<const float4*>(Ar + j * 4);
}

// warps 0-3: split regs -> TMEM A[buf] (hi at +0, lo at +32), thread = row/lane
__device__ __forceinline__ void convA_tmem(const float4 (&r)[16], uint32_t atm, int row) {
    uint32_t hi[32], lo[32];
    #pragma unroll
    for (int j = 0; j < 16; j++) {
        const float4 v = r[j];
        __nv_bfloat162 h01 = __float22bfloat162_rn(make_float2(v.x, v.y));
        __nv_bfloat162 h23 = __float22bfloat162_rn(make_float2(v.z, v.w));
        float2 f01 = __bfloat1622float2(h01);
        float2 f23 = __bfloat1622float2(h23);
        __nv_bfloat162 l01 = __float22bfloat162_rn(make_float2(v.x - f01.x, v.y - f01.y));
        __nv_bfloat162 l23 = __float22bfloat162_rn(make_float2(v.z - f23.x, v.w - f23.y));
        hi[2*j]   = reinterpret_cast<uint32_t&>(h01);
        hi[2*j+1] = reinterpret_cast<uint32_t&>(h23);
        lo[2*j]   = reinterpret_cast<uint32_t&>(l01);
        lo[2*j+1] = reinterpret_cast<uint32_t&>(l23);
    }
    const uint32_t woff = ((uint32_t)row >> 5) << 21;   // subpartition select
    STTM_X32(atm + woff, hi);
    STTM_X32(atm + 32 + woff, lo);
    TC_WAIT_ST();
}

// all 256 threads: cp.async one chunk of Bh+Bl into stage s
__device__ __forceinline__ void loadB_chunk(uint32_t sb, int c, int s,
                                            const __nv_bfloat16* __restrict__ Bhb,
                                            const __nv_bfloat16* __restrict__ Blb,
                                            int tid) {
    const uint32_t bh = sb + OFF_B + (uint32_t)s * B_STAGE;
    const uint32_t bl = bh + 32768u;
    const __nv_bfloat16* Bhc = Bhb + c * BK;
    const __nv_bfloat16* Blc = Blb + c * BK;
    #pragma unroll
    for (int i = 0; i < 8; i++) {
        const uint32_t idx = (uint32_t)(tid + i * NTHR);   // 0..2047
        const uint32_t row = idx >> 3, j = idx & 7;
        const uint32_t off = row * 128u + j * 16u;
        const uint32_t sw = off ^ ((off >> 3) & 0x70);
        cp16(bh + sw, Bhc + (size_t)row * K_ + j * 8);
        cp16(bl + sw, Blc + (size_t)row * K_ + j * 8);
    }
}
#endif // !TC_FALLBACK

__global__ void __launch_bounds__(NTHR, 1)
grouped_gemm_tc(const float* __restrict__ A, const int* __restrict__ ent,
                float* __restrict__ C) {
    const int e  = blockIdx.z;
    const int m0 = blockIdx.y * BM;
    const int n0 = blockIdx.x * BN;
    const int nt = __ldg(&ent[e]);
    const int tid = threadIdx.x;
    const int wid = tid >> 5;
    const int lid = tid & 31;

    float* __restrict__ Ce = C + (size_t)e * M_ * N_;

    // ---- fully-invalid tile: vectorized zero-fill ----
    if (m0 >= nt) {
        const float4 z = make_float4(0.f, 0.f, 0.f, 0.f);
        #pragma unroll 8
        for (int i = tid; i < BM * (BN / 4); i += NTHR) {
            const int r = i >> 6;
            const int c4 = (i & 63) << 2;
            *reinterpret_cast<float4*>(&Ce[(size_t)(m0 + r) * N_ + n0 + c4]) = z;
        }
        return;
    }

#if TC_FALLBACK
    // ---- portable-PTX fallback (never executed on GB300) ----
    const __nv_bfloat16* Bh = g_Bh + ((size_t)e * N_ + n0) * K_;
    const __nv_bfloat16* Bl = g_Bl + ((size_t)e * N_ + n0) * K_;
    const float* Ae = A + ((size_t)e * M_ + m0) * K_;
    for (int r = tid; r < BM; r += NTHR) {
        const int m = m0 + r;
        const bool valid = m < nt;
        for (int n = 0; n < BN; n++) {
            float acc = 0.f;
            if (valid) {
                for (int k = 0; k < K_; k++) {
                    float b = __bfloat162float(Bh[(size_t)n * K_ + k]) +
                              __bfloat162float(Bl[(size_t)n * K_ + k]);
                    acc = fmaf(Ae[(size_t)r * K_ + k], b, acc);
                }
            }
            Ce[(size_t)m * N_ + n0 + n] = acc;
        }
    }
#else
    extern __shared__ char smem[];
    const uint32_t sb = smem_u32(smem);
    const bool aWarp = (tid < 128);

    const float* Ab = A + ((size_t)e * M_ + m0) * K_;
    const __nv_bfloat16* Bhb = g_Bh + ((size_t)e * N_ + n0) * K_;
    const __nv_bfloat16* Blb = g_Bl + ((size_t)e * N_ + n0) * K_;

    // B pipeline prologue: chunks 0,1 (groups 0,1) — before TMEM alloc for earliest start
    loadB_chunk(sb, 0, 0, Bhb, Blb, tid); CP_COMMIT();
    loadB_chunk(sb, 1, 1, Bhb, Blb, tid); CP_COMMIT();

    if (tid == 0) {
        MBAR_INIT(sb + SM_MBAR0, 1);
        MBAR_INIT(sb + SM_MBAR1, 1);
    }
    if (wid == 0) TC_ALLOC(sb + SM_TMEM, TMEM_COLS);
    __syncthreads();
    uint32_t tmem;
    asm volatile("ld.shared.b32 %0, [%1];" : "=r"(tmem) : "r"(sb + SM_TMEM));

    // A prologue: chunks 0,1 into reg double buffer; convert chunk 0 -> A TMEM[0]
    float4 ar0[16], ar1[16];
    if (aWarp) {
        loadA_regs(ar0, Ab, 0, tid);
        loadA_regs(ar1, Ab, 1, tid);
        convA_tmem(ar0, tmem + TM_A_OFF + 0 * 64, tid);
        TC_FENCE_BEFORE();
    }

    int wcnt0 = 0, wcnt1 = 0;

    #pragma unroll
    for (int c = 0; c < NCHUNK; c++) {
        // wait MMA c-1 done: frees A TMEM[(c+1)&1] and B stage (c+2)%3
        if (c >= 1) {
            if (((c - 1) & 1) == 0) { mbar_wait(sb + SM_MBAR0, wcnt0 & 1); wcnt0++; }
            else                    { mbar_wait(sb + SM_MBAR1, wcnt1 & 1); wcnt1++; }
        }
        // issue B chunk c+2 (2 periods ahead)
        if (c + 2 < NCHUNK) {
            loadB_chunk(sb, c + 2, (c + 2) % 3, Bhb, Blb, tid);
            CP_COMMIT();
        }
        // A: LDG chunk c+2 into the reg buffer freed by last iter's convert
        if (aWarp && c + 2 < NCHUNK) {
            if ((c & 1) == 0) loadA_regs(ar0, Ab, c + 2, tid);
            else              loadA_regs(ar1, Ab, c + 2, tid);
        }
        // ensure B chunk c arrived (per-thread)
        if (c <= NCHUNK - 3)      CP_WAIT2();
        else if (c == NCHUNK - 2) CP_WAIT1();
        else                      CP_WAIT0();
        // A: convert chunk c+1 -> TMEM A[(c+1)&1]
        if (aWarp && c + 1 < NCHUNK) {
            if (((c + 1) & 1) == 0) convA_tmem(ar0, tmem + TM_A_OFF + 0 * 64, tid);
            else                    convA_tmem(ar1, tmem + TM_A_OFF + 1 * 64, tid);
            TC_FENCE_BEFORE();
        }
        __syncthreads();

        if (wid == 0 && elect_one()) {
            TC_FENCE_AFTER();
            FENCE_ASYNC();
            const uint32_t atm = tmem + TM_A_OFF + (uint32_t)(c & 1) * 64u;
            const uint32_t bst = sb + OFF_B + (uint32_t)(c % 3) * B_STAGE;
            const uint64_t dBh = sdesc(bst);
            const uint64_t dBl = sdesc(bst + 32768u);
            #pragma unroll
            for (int ks = 0; ks < 4; ks++) {        // 4 x K=16 per 64-chunk
                const uint64_t o = (uint64_t)(ks * 2);
                mma_f16_ts(tmem, atm + ks * 8,      dBh + o, IDESC, (c == 0 && ks == 0) ? 0u : 1u);
                mma_f16_ts(tmem, atm + ks * 8,      dBl + o, IDESC, 1u);
                mma_f16_ts(tmem, atm + 32 + ks * 8, dBh + o, IDESC, 1u);
            }
            TC_COMMIT(sb + ((c & 1) ? SM_MBAR1 : SM_MBAR0));
        }
    }

    // final commit (chunk 7) -> mbar1; in-order completion covers all MMAs
    mbar_wait(sb + SM_MBAR1, wcnt1 & 1);
    TC_FENCE_AFTER();

    // epilogue: warps 0-3 read D (TMEM cols 0..255), mask invalid rows
    if (wid < 4) {
        const int m = m0 + wid * 32 + lid;
        const bool valid = m < nt;
        float* crow = Ce + (size_t)m * N_ + n0;
        const float4 z = make_float4(0.f, 0.f, 0.f, 0.f);
        #pragma unroll
        for (int cb = 0; cb < BN; cb += 32) {
            uint32_t r[32];
            LDTM_X32(r, tmem + cb);
            TC_WAIT_LD();
            #pragma unroll
            for (int j = 0; j < 8; j++) {
                float4 v;
                if (valid) {
                    v = make_float4(__uint_as_float(r[j * 4 + 0]), __uint_as_float(r[j * 4 + 1]),
                                    __uint_as_float(r[j * 4 + 2]), __uint_as_float(r[j * 4 + 3]));
                } else {
                    v = z;
                }
                *reinterpret_cast<float4*>(crow + cb + j * 4) = v;
            }
        }
    }

    __syncthreads();
    if (tid == 0) { MBAR_INVAL(sb + SM_MBAR0); MBAR_INVAL(sb + SM_MBAR1); }
    __syncthreads();
    if (wid == 0) {
        TC_RELINQ();
        TC_DEALLOC(tmem, TMEM_COLS);
    }
#endif
}

// ======================= launch =======================
extern "C" void kernel_launch(void* const* d_in, const int* in_sizes, int n_in,
                              void* d_out, int out_size)
{
    const float* A   = (const float*)d_in[0];   // [E, M, K]
    const float* B   = (const float*)d_in[1];   // [E, N, K]
    const int*   ent = (const int*)d_in[2];     // [E]
    float*       C   = (float*)d_out;           // [E, M, N]

    convertB<<<1024, 256>>>(B);

    cudaFuncSetAttribute(grouped_gemm_tc,
                         cudaFuncAttributeMaxDynamicSharedMemorySize, SMEM_TOTAL);
    dim3 grid(N_ / BN, M_ / BM, E_);   // (2, 8, 32)
    grouped_gemm_tc<<<grid, NTHR, SMEM_TOTAL>>>(A, ent, C);
}

// round 7
// speedup vs baseline: 1.1336x; 1.1336x over previous
#include <cuda_runtime.h>
#include <cuda_bf16.h>
#include <cstdint>

// Grouped GEMM C[e] = A[e] @ B[e]^T via tcgen05 bf16-split (3-MMA fp32 emulation).
// E=32, M=1024, K=512, N=512 fp32. Rows m >= expert_num_tokens[e] -> 0.
//
// R7: R5's SS pipeline, resized for 2 CTAs/SM: BK=32 (64B rows, SW64 swizzle),
// stage = Ah8+Al8+Bh16+Bl16 = 48KB, 2 stages = ~97KB/CTA. B pre-split scratch,
// A converted in-kernel from registers. tcgen05 guarded for compute_103 pass.

#define E_ 32
#define M_ 1024
#define K_ 512
#define N_ 512

#define BM 128
#define BN 256
#define BK 32            // k-elems per chunk (64B bf16 rows -> SW64)
#define NCHUNK (K_/BK)   // 16
#define NTHR 256

#if defined(__CUDA_ARCH__) && !defined(__CUDA_ARCH_FEAT_SM103_ALL) && !defined(__CUDA_ARCH_FEAT_SM100_ALL)
#define TC_FALLBACK 1
#else
#define TC_FALLBACK 0
#endif

// ---- scratch: bf16 hi/lo split of B only ----
__device__ __align__(16) __nv_bfloat16 g_Bh[E_*N_*K_];
__device__ __align__(16) __nv_bfloat16 g_Bl[E_*N_*K_];

// ======================= portable PTX helpers =======================
__device__ __forceinline__ uint32_t smem_u32(const void* p) {
    uint32_t a;
    asm("{ .reg .u64 t; cvta.to.shared.u64 t, %1; cvt.u32.u64 %0, t; }" : "=r"(a) : "l"(p));
    return a;
}
__device__ __forceinline__ uint32_t elect_one() {
    uint32_t pred;
    asm volatile("{ .reg .pred p; elect.sync _|p, 0xFFFFFFFF; selp.b32 %0, 1, 0, p; }" : "=r"(pred));
    return pred;
}
#define MBAR_INIT(addr, cnt) \
    asm volatile("mbarrier.init.shared.b64 [%0], %1;" :: "r"(addr), "r"(cnt) : "memory")
#define MBAR_INVAL(addr) \
    asm volatile("mbarrier.inval.shared.b64 [%0];" :: "r"(addr) : "memory")

__device__ __forceinline__ void mbar_wait(uint32_t mbar, uint32_t parity) {
    uint32_t done;
    asm volatile("{ .reg .pred p; mbarrier.try_wait.parity.acquire.cta.shared::cta.b64 p, [%1], %2; selp.b32 %0,1,0,p; }"
                 : "=r"(done) : "r"(mbar), "r"(parity) : "memory");
    if (!done) {
        asm volatile("{ .reg .pred P1;\n"
                     "WL_%=: mbarrier.try_wait.parity.acquire.cta.shared::cta.b64 P1, [%0], %1, 0x989680;\n"
                     "@P1 bra.uni WD_%=;\n bra.uni WL_%=;\n WD_%=: }"
                     :: "r"(mbar), "r"(parity) : "memory");
    }
}

__device__ __forceinline__ void cp16(uint32_t s, const void* g) {
    asm volatile("cp.async.cg.shared.global [%0], [%1], 16;" :: "r"(s), "l"(g));
}
#define CP_COMMIT() asm volatile("cp.async.commit_group;" ::: "memory")
#define CP_WAIT0()  asm volatile("cp.async.wait_group 0;" ::: "memory")
#define CP_WAIT1()  asm volatile("cp.async.wait_group 1;" ::: "memory")
#define FENCE_ASYNC() asm volatile("fence.proxy.async.shared::cta;" ::: "memory")

// ======================= tcgen05 helpers (sm_103a pass only) =======================
#if !TC_FALLBACK
#define TC_ALLOC(smem_addr, ncols) \
    asm volatile("tcgen05.alloc.cta_group::1.sync.aligned.shared::cta.b32 [%0], %1;" \
                 :: "r"(smem_addr), "r"(ncols) : "memory")
#define TC_DEALLOC(tmem, ncols) \
    asm volatile("tcgen05.dealloc.cta_group::1.sync.aligned.b32 %0, %1;" :: "r"(tmem), "r"(ncols))
#define TC_RELINQ() \
    asm volatile("tcgen05.relinquish_alloc_permit.cta_group::1.sync.aligned;")
#define TC_COMMIT(mbar) \
    asm volatile("tcgen05.commit.cta_group::1.mbarrier::arrive::one.shared::cluster.b64 [%0];" \
                 :: "r"(mbar) : "memory")
#define TC_FENCE_AFTER()  asm volatile("tcgen05.fence::after_thread_sync;" ::: "memory")
#define TC_WAIT_LD()      asm volatile("tcgen05.wait::ld.sync.aligned;" ::: "memory")

__device__ __forceinline__ void mma_f16_ss(uint32_t d, uint64_t ad, uint64_t bd,
                                           uint32_t idesc, uint32_t enable) {
    asm volatile("{ .reg .pred p; setp.ne.u32 p, %5, 0;\n"
                 "tcgen05.mma.cta_group::1.kind::f16 [%0], %1, %2, %3, {%4,%4,%4,%4}, p; }"
                 :: "r"(d), "l"(ad), "l"(bd), "r"(idesc), "r"(0u), "r"(enable) : "memory");
}

#define LDTM_X32(r, addr) \
    asm volatile("tcgen05.ld.sync.aligned.32x32b.x32.b32 " \
        "{%0,%1,%2,%3,%4,%5,%6,%7,%8,%9,%10,%11,%12,%13,%14,%15," \
        "%16,%17,%18,%19,%20,%21,%22,%23,%24,%25,%26,%27,%28,%29,%30,%31}, [%32];" \
        : "=r"((r)[0]),"=r"((r)[1]),"=r"((r)[2]),"=r"((r)[3]),"=r"((r)[4]),"=r"((r)[5]),"=r"((r)[6]),"=r"((r)[7]), \
          "=r"((r)[8]),"=r"((r)[9]),"=r"((r)[10]),"=r"((r)[11]),"=r"((r)[12]),"=r"((r)[13]),"=r"((r)[14]),"=r"((r)[15]), \
          "=r"((r)[16]),"=r"((r)[17]),"=r"((r)[18]),"=r"((r)[19]),"=r"((r)[20]),"=r"((r)[21]),"=r"((r)[22]),"=r"((r)[23]), \
          "=r"((r)[24]),"=r"((r)[25]),"=r"((r)[26]),"=r"((r)[27]),"=r"((r)[28]),"=r"((r)[29]),"=r"((r)[30]),"=r"((r)[31]) \
        : "r"(addr))
#endif // !TC_FALLBACK

// SW64 K-major descriptor (layout=4, version=1, SBO=32, LBO=1); 64B rows
static constexpr uint64_t DESC_SW64 =
    (4ull << 61) | (1ull << 46) | (32ull << 32) | (1ull << 16);
__device__ __forceinline__ uint64_t sdesc64(uint32_t a) {
    return DESC_SW64 | ((uint64_t)(a >> 4) & 0x3FFF);
}
__device__ __forceinline__ uint32_t sw64(uint32_t off) {
    return off ^ ((off >> 3) & 0x30);
}

// idesc: F32 accum, BF16 x BF16, M=128, N=256, K-major both
static constexpr uint32_t IDESC =
    (1u << 4) | (1u << 7) | (1u << 10) | ((BN / 8) << 17) | ((BM / 16) << 24);

// ======================= B conversion prepass =======================
__global__ void __launch_bounds__(256) convertB(const float* __restrict__ B) {
    const uint32_t nvec = (uint32_t)(E_ * N_ * K_ / 4);
    const uint32_t stride = gridDim.x * blockDim.x;
    for (uint32_t i = blockIdx.x * blockDim.x + threadIdx.x; i < nvec; i += stride) {
        const uint32_t elem = i * 4;
        const float4 v = *reinterpret_cast<const float4*>(B + elem);
        __nv_bfloat162 h01 = __float22bfloat162_rn(make_float2(v.x, v.y));
        __nv_bfloat162 h23 = __float22bfloat162_rn(make_float2(v.z, v.w));
        float2 f01 = __bfloat1622float2(h01);
        float2 f23 = __bfloat1622float2(h23);
        __nv_bfloat162 l01 = __float22bfloat162_rn(make_float2(v.x - f01.x, v.y - f01.y));
        __nv_bfloat162 l23 = __float22bfloat162_rn(make_float2(v.z - f23.x, v.w - f23.y));
        uint2 hu, lu;
        hu.x = reinterpret_cast<uint32_t&>(h01); hu.y = reinterpret_cast<uint32_t&>(h23);
        lu.x = reinterpret_cast<uint32_t&>(l01); lu.y = reinterpret_cast<uint32_t&>(l23);
        *reinterpret_cast<uint2*>(&g_Bh[elem]) = hu;
        *reinterpret_cast<uint2*>(&g_Bl[elem]) = lu;
    }
}

// ======================= fused GEMM =======================
// SMEM per CTA (~97KB -> 2 CTAs/SM):
//   [0] tmem ptr; [16],[24] mbarriers
//   stage s at 1024 + s*49152:
//     AH +0     (8KB : 128 rows x 64B, SW64)
//     AL +8192
//     BH +16384 (16KB: 256 rows x 64B, SW64)
//     BL +32768
#define SM_TMEM 0
#define SM_MBAR0 16
#define SM_MBAR1 24
#define OFF_STAGE 1024
#define STAGE_BYTES 49152
#define OFF_AH 0
#define OFF_AL 8192
#define OFF_BH 16384
#define OFF_BL 32768
#define SMEM_TOTAL (1024 + 2 * STAGE_BYTES)   // 99328
#define TMEM_COLS 256

#if !TC_FALLBACK
// LDG chunk c of A into registers (4 x float4 per thread)
__device__ __forceinline__ void loadA_regs(float4 (&r)[4], const float* __restrict__ Ab,
                                           int c, int tid) {
    const float* Ac = Ab + c * BK;
    #pragma unroll
    for (int i = 0; i < 4; i++) {
        const uint32_t idx = (uint32_t)(tid + i * NTHR);   // 0..1023
        const uint32_t row = idx >> 3, j = idx & 7;        // 128 rows x 8 float4
        r[i] = *reinterpret_cast<const float4*>(Ac + (size_t)row * K_ + j * 4);
    }
}

// split registers -> Ah/Al[stage] smem (SW64)
__device__ __forceinline__ void convA_regs(const float4 (&r)[4], uint32_t stg, int tid) {
    const uint32_t ah = stg + OFF_AH;
    const uint32_t al = stg + OFF_AL;
    #pragma unroll
    for (int i = 0; i < 4; i++) {
        const float4 v = r[i];
        __nv_bfloat162 h01 = __float22bfloat162_rn(make_float2(v.x, v.y));
        __nv_bfloat162 h23 = __float22bfloat162_rn(make_float2(v.z, v.w));
        float2 f01 = __bfloat1622float2(h01);
        float2 f23 = __bfloat1622float2(h23);
        __nv_bfloat162 l01 = __float22bfloat162_rn(make_float2(v.x - f01.x, v.y - f01.y));
        __nv_bfloat162 l23 = __float22bfloat162_rn(make_float2(v.z - f23.x, v.w - f23.y));
        const uint32_t idx = (uint32_t)(tid + i * NTHR);
        const uint32_t row = idx >> 3, j = idx & 7;        // j*4 floats -> col j*4
        const uint32_t off = row * 64u + j * 8u;           // 4 bf16 = 8 bytes
        const uint32_t sw = sw64(off);
        asm volatile("st.shared.v2.b32 [%0], {%1,%2};"
                     :: "r"(ah + sw), "r"(reinterpret_cast<const uint32_t&>(h01)),
                        "r"(reinterpret_cast<const uint32_t&>(h23)) : "memory");
        asm volatile("st.shared.v2.b32 [%0], {%1,%2};"
                     :: "r"(al + sw), "r"(reinterpret_cast<const uint32_t&>(l01)),
                        "r"(reinterpret_cast<const uint32_t&>(l23)) : "memory");
    }
}

// cp.async chunk c of Bh/Bl into stage
__device__ __forceinline__ void loadB_chunk(uint32_t stg, int c,
                                            const __nv_bfloat16* __restrict__ Bhb,
                                            const __nv_bfloat16* __restrict__ Blb,
                                            int tid) {
    const uint32_t bh = stg + OFF_BH;
    const uint32_t bl = stg + OFF_BL;
    const __nv_bfloat16* Bhc = Bhb + c * BK;
    const __nv_bfloat16* Blc = Blb + c * BK;
    #pragma unroll
    for (int i = 0; i < 4; i++) {
        const uint32_t idx = (uint32_t)(tid + i * NTHR);   // 0..1023
        const uint32_t row = idx >> 2, j = idx & 3;        // 256 rows x 4 x 16B
        const uint32_t off = row * 64u + j * 16u;
        const uint32_t sw = sw64(off);
        cp16(bh + sw, Bhc + (size_t)row * K_ + j * 8);
        cp16(bl + sw, Blc + (size_t)row * K_ + j * 8);
    }
}
#endif // !TC_FALLBACK

__global__ void __launch_bounds__(NTHR, 2)
grouped_gemm_tc(const float* __restrict__ A, const int* __restrict__ ent,
                float* __restrict__ C) {
    const int e  = blockIdx.z;
    const int m0 = blockIdx.y * BM;
    const int n0 = blockIdx.x * BN;
    const int nt = __ldg(&ent[e]);
    const int tid = threadIdx.x;
    const int wid = tid >> 5;
    const int lid = tid & 31;

    float* __restrict__ Ce = C + (size_t)e * M_ * N_;

    // ---- fully-invalid tile: vectorized zero-fill ----
    if (m0 >= nt) {
        const float4 z = make_float4(0.f, 0.f, 0.f, 0.f);
        #pragma unroll 8
        for (int i = tid; i < BM * (BN / 4); i += NTHR) {
            const int r = i >> 6;
            const int c4 = (i & 63) << 2;
            *reinterpret_cast<float4*>(&Ce[(size_t)(m0 + r) * N_ + n0 + c4]) = z;
        }
        return;
    }

#if TC_FALLBACK
    // ---- portable-PTX fallback (never executed on GB300) ----
    const __nv_bfloat16* Bh = g_Bh + ((size_t)e * N_ + n0) * K_;
    const __nv_bfloat16* Bl = g_Bl + ((size_t)e * N_ + n0) * K_;
    const float* Ae = A + ((size_t)e * M_ + m0) * K_;
    for (int r = tid; r < BM; r += NTHR) {
        const int m = m0 + r;
        const bool valid = m < nt;
        for (int n = 0; n < BN; n++) {
            float acc = 0.f;
            if (valid) {
                for (int k = 0; k < K_; k++) {
                    float b = __bfloat162float(Bh[(size_t)n * K_ + k]) +
                              __bfloat162float(Bl[(size_t)n * K_ + k]);
                    acc = fmaf(Ae[(size_t)r * K_ + k], b, acc);
                }
            }
            Ce[(size_t)m * N_ + n0 + n] = acc;
        }
    }
#else
    extern __shared__ char smem[];
    const uint32_t sb = smem_u32(smem);

    if (tid == 0) {
        MBAR_INIT(sb + SM_MBAR0, 1);
        MBAR_INIT(sb + SM_MBAR1, 1);
    }
    if (wid == 0) TC_ALLOC(sb + SM_TMEM, TMEM_COLS);
    __syncthreads();
    uint32_t tmem;
    asm volatile("ld.shared.b32 %0, [%1];" : "=r"(tmem) : "r"(sb + SM_TMEM));

    const float* Ab = A + ((size_t)e * M_ + m0) * K_;
    const __nv_bfloat16* Bhb = g_Bh + ((size_t)e * N_ + n0) * K_;
    const __nv_bfloat16* Blb = g_Bl + ((size_t)e * N_ + n0) * K_;

    float4 ar0[4], ar1[4];   // double-buffered A registers

    // prologue: chunk 0 -> stage 0
    loadA_regs(ar0, Ab, 0, tid);
    loadB_chunk(sb + OFF_STAGE, 0, Bhb, Blb, tid);
    CP_COMMIT();

    int wcnt0 = 0, wcnt1 = 0;

    #pragma unroll 1
    for (int c = 0; c < NCHUNK; c++) {
        const int buf = c & 1;
        const uint32_t stg = sb + OFF_STAGE + (uint32_t)buf * STAGE_BYTES;
        if (c + 1 < NCHUNK) {
            const int nb = (c + 1) & 1;
            // A LDG first: regs don't alias smem, overlaps the mbar wait below
            if (nb == 0) loadA_regs(ar0, Ab, c + 1, tid);
            else         loadA_regs(ar1, Ab, c + 1, tid);
            // stage nb last read by MMA chunk c-1 -> wait it before overwrite
            if (c >= 1) {
                if (((c - 1) & 1) == 0) { mbar_wait(sb + SM_MBAR0, wcnt0 & 1); wcnt0++; }
                else                    { mbar_wait(sb + SM_MBAR1, wcnt1 & 1); wcnt1++; }
            }
            loadB_chunk(sb + OFF_STAGE + (uint32_t)nb * STAGE_BYTES, c + 1, Bhb, Blb, tid);
            CP_COMMIT();
            CP_WAIT1();     // chunk c's B arrived (chunk c+1 still in flight)
        } else {
            CP_WAIT0();
        }

        // convert A chunk c into stage buf (freed by MMA c-2 wait above)
        if (buf == 0) convA_regs(ar0, stg, tid);
        else          convA_regs(ar1, stg, tid);

        __syncthreads();
        FENCE_ASYNC();

        if (wid == 0 && elect_one()) {
            const uint64_t dAh = sdesc64(stg + OFF_AH);
            const uint64_t dAl = sdesc64(stg + OFF_AL);
            const uint64_t dBh = sdesc64(stg + OFF_BH);
            const uint64_t dBl = sdesc64(stg + OFF_BL);
            #pragma unroll
            for (int ks = 0; ks < 2; ks++) {        // 2 x K=16 per 32-chunk
                const uint64_t o = (uint64_t)(ks * 2);
                mma_f16_ss(tmem, dAh + o, dBh + o, IDESC, (c == 0 && ks == 0) ? 0u : 1u);
                mma_f16_ss(tmem, dAh + o, dBl + o, IDESC, 1u);
                mma_f16_ss(tmem, dAl + o, dBh + o, IDESC, 1u);
            }
            TC_COMMIT(sb + (buf ? SM_MBAR1 : SM_MBAR0));
        }
        __syncthreads();
    }

    // final chunk (15) committed to mbar1 — in-order completion covers all MMAs
    mbar_wait(sb + SM_MBAR1, wcnt1 & 1);
    TC_FENCE_AFTER();

    // epilogue: warps 0-3 read D (TMEM cols 0..255), mask invalid rows
    if (wid < 4) {
        const int m = m0 + wid * 32 + lid;
        const bool valid = m < nt;
        float* crow = Ce + (size_t)m * N_ + n0;
        const float4 z = make_float4(0.f, 0.f, 0.f, 0.f);
        #pragma unroll
        for (int cb = 0; cb < BN; cb += 32) {
            uint32_t r[32];
            LDTM_X32(r, tmem + cb);
            TC_WAIT_LD();
            #pragma unroll
            for (int j = 0; j < 8; j++) {
                float4 v;
                if (valid) {
                    v = make_float4(__uint_as_float(r[j * 4 + 0]), __uint_as_float(r[j * 4 + 1]),
                                    __uint_as_float(r[j * 4 + 2]), __uint_as_float(r[j * 4 + 3]));
                } else {
                    v = z;
                }
                *reinterpret_cast<float4*>(crow + cb + j * 4) = v;
            }
        }
    }

    __syncthreads();
    if (tid == 0) { MBAR_INVAL(sb + SM_MBAR0); MBAR_INVAL(sb + SM_MBAR1); }
    __syncthreads();
    if (wid == 0) {
        TC_RELINQ();
        TC_DEALLOC(tmem, TMEM_COLS);
    }
#endif
}

// ======================= launch =======================
extern "C" void kernel_launch(void* const* d_in, const int* in_sizes, int n_in,
                              void* d_out, int out_size)
{
    const float* A   = (const float*)d_in[0];   // [E, M, K]
    const float* B   = (const float*)d_in[1];   // [E, N, K]
    const int*   ent = (const int*)d_in[2];     // [E]
    float*       C   = (float*)d_out;           // [E, M, N]

    convertB<<<1024, 256>>>(B);

    cudaFuncSetAttribute(grouped_gemm_tc,
                         cudaFuncAttributeMaxDynamicSharedMemorySize, SMEM_TOTAL);
    dim3 grid(N_ / BN, M_ / BM, E_);   // (2, 8, 32)
    grouped_gemm_tc<<<grid, NTHR, SMEM_TOTAL>>>(A, ent, C);
}

// round 8
// speedup vs baseline: 1.4090x; 1.2429x over previous
#include <cuda_runtime.h>
#include <cuda_bf16.h>
#include <cstdint>

// Grouped GEMM C[e] = A[e] @ B[e]^T via tcgen05 bf16-split (3-MMA fp32 emulation).
// E=32, M=1024, K=512, N=512 fp32. Rows m >= expert_num_tokens[e] -> 0.
//
// R8 = R7 + relinquish the TMEM alloc permit right after tcgen05.alloc so a
// second CTA can co-reside on the SM (2 CTAs/SM: BK=32, SW64, ~97KB smem,
// 256 TMEM cols each). B pre-split scratch; A converted in-kernel.

#define E_ 32
#define M_ 1024
#define K_ 512
#define N_ 512

#define BM 128
#define BN 256
#define BK 32            // k-elems per chunk (64B bf16 rows -> SW64)
#define NCHUNK (K_/BK)   // 16
#define NTHR 256

#if defined(__CUDA_ARCH__) && !defined(__CUDA_ARCH_FEAT_SM103_ALL) && !defined(__CUDA_ARCH_FEAT_SM100_ALL)
#define TC_FALLBACK 1
#else
#define TC_FALLBACK 0
#endif

// ---- scratch: bf16 hi/lo split of B only ----
__device__ __align__(16) __nv_bfloat16 g_Bh[E_*N_*K_];
__device__ __align__(16) __nv_bfloat16 g_Bl[E_*N_*K_];

// ======================= portable PTX helpers =======================
__device__ __forceinline__ uint32_t smem_u32(const void* p) {
    uint32_t a;
    asm("{ .reg .u64 t; cvta.to.shared.u64 t, %1; cvt.u32.u64 %0, t; }" : "=r"(a) : "l"(p));
    return a;
}
__device__ __forceinline__ uint32_t elect_one() {
    uint32_t pred;
    asm volatile("{ .reg .pred p; elect.sync _|p, 0xFFFFFFFF; selp.b32 %0, 1, 0, p; }" : "=r"(pred));
    return pred;
}
#define MBAR_INIT(addr, cnt) \
    asm volatile("mbarrier.init.shared.b64 [%0], %1;" :: "r"(addr), "r"(cnt) : "memory")
#define MBAR_INVAL(addr) \
    asm volatile("mbarrier.inval.shared.b64 [%0];" :: "r"(addr) : "memory")

__device__ __forceinline__ void mbar_wait(uint32_t mbar, uint32_t parity) {
    uint32_t done;
    asm volatile("{ .reg .pred p; mbarrier.try_wait.parity.acquire.cta.shared::cta.b64 p, [%1], %2; selp.b32 %0,1,0,p; }"
                 : "=r"(done) : "r"(mbar), "r"(parity) : "memory");
    if (!done) {
        asm volatile("{ .reg .pred P1;\n"
                     "WL_%=: mbarrier.try_wait.parity.acquire.cta.shared::cta.b64 P1, [%0], %1, 0x989680;\n"
                     "@P1 bra.uni WD_%=;\n bra.uni WL_%=;\n WD_%=: }"
                     :: "r"(mbar), "r"(parity) : "memory");
    }
}

__device__ __forceinline__ void cp16(uint32_t s, const void* g) {
    asm volatile("cp.async.cg.shared.global [%0], [%1], 16;" :: "r"(s), "l"(g));
}
#define CP_COMMIT() asm volatile("cp.async.commit_group;" ::: "memory")
#define CP_WAIT0()  asm volatile("cp.async.wait_group 0;" ::: "memory")
#define CP_WAIT1()  asm volatile("cp.async.wait_group 1;" ::: "memory")
#define FENCE_ASYNC() asm volatile("fence.proxy.async.shared::cta;" ::: "memory")

// ======================= tcgen05 helpers (sm_103a pass only) =======================
#if !TC_FALLBACK
#define TC_ALLOC(smem_addr, ncols) \
    asm volatile("tcgen05.alloc.cta_group::1.sync.aligned.shared::cta.b32 [%0], %1;" \
                 :: "r"(smem_addr), "r"(ncols) : "memory")
#define TC_DEALLOC(tmem, ncols) \
    asm volatile("tcgen05.dealloc.cta_group::1.sync.aligned.b32 %0, %1;" :: "r"(tmem), "r"(ncols))
#define TC_RELINQ() \
    asm volatile("tcgen05.relinquish_alloc_permit.cta_group::1.sync.aligned;")
#define TC_COMMIT(mbar) \
    asm volatile("tcgen05.commit.cta_group::1.mbarrier::arrive::one.shared::cluster.b64 [%0];" \
                 :: "r"(mbar) : "memory")
#define TC_FENCE_AFTER()  asm volatile("tcgen05.fence::after_thread_sync;" ::: "memory")
#define TC_WAIT_LD()      asm volatile("tcgen05.wait::ld.sync.aligned;" ::: "memory")

__device__ __forceinline__ void mma_f16_ss(uint32_t d, uint64_t ad, uint64_t bd,
                                           uint32_t idesc, uint32_t enable) {
    asm volatile("{ .reg .pred p; setp.ne.u32 p, %5, 0;\n"
                 "tcgen05.mma.cta_group::1.kind::f16 [%0], %1, %2, %3, {%4,%4,%4,%4}, p; }"
                 :: "r"(d), "l"(ad), "l"(bd), "r"(idesc), "r"(0u), "r"(enable) : "memory");
}

#define LDTM_X32(r, addr) \
    asm volatile("tcgen05.ld.sync.aligned.32x32b.x32.b32 " \
        "{%0,%1,%2,%3,%4,%5,%6,%7,%8,%9,%10,%11,%12,%13,%14,%15," \
        "%16,%17,%18,%19,%20,%21,%22,%23,%24,%25,%26,%27,%28,%29,%30,%31}, [%32];" \
        : "=r"((r)[0]),"=r"((r)[1]),"=r"((r)[2]),"=r"((r)[3]),"=r"((r)[4]),"=r"((r)[5]),"=r"((r)[6]),"=r"((r)[7]), \
          "=r"((r)[8]),"=r"((r)[9]),"=r"((r)[10]),"=r"((r)[11]),"=r"((r)[12]),"=r"((r)[13]),"=r"((r)[14]),"=r"((r)[15]), \
          "=r"((r)[16]),"=r"((r)[17]),"=r"((r)[18]),"=r"((r)[19]),"=r"((r)[20]),"=r"((r)[21]),"=r"((r)[22]),"=r"((r)[23]), \
          "=r"((r)[24]),"=r"((r)[25]),"=r"((r)[26]),"=r"((r)[27]),"=r"((r)[28]),"=r"((r)[29]),"=r"((r)[30]),"=r"((r)[31]) \
        : "r"(addr))
#endif // !TC_FALLBACK

// SW64 K-major descriptor (layout=4, version=1, SBO=32, LBO=1); 64B rows
static constexpr uint64_t DESC_SW64 =
    (4ull << 61) | (1ull << 46) | (32ull << 32) | (1ull << 16);
__device__ __forceinline__ uint64_t sdesc64(uint32_t a) {
    return DESC_SW64 | ((uint64_t)(a >> 4) & 0x3FFF);
}
__device__ __forceinline__ uint32_t sw64(uint32_t off) {
    return off ^ ((off >> 3) & 0x30);
}

// idesc: F32 accum, BF16 x BF16, M=128, N=256, K-major both
static constexpr uint32_t IDESC =
    (1u << 4) | (1u << 7) | (1u << 10) | ((BN / 8) << 17) | ((BM / 16) << 24);

// ======================= B conversion prepass =======================
__global__ void __launch_bounds__(256) convertB(const float* __restrict__ B) {
    const uint32_t nvec = (uint32_t)(E_ * N_ * K_ / 4);
    const uint32_t stride = gridDim.x * blockDim.x;
    for (uint32_t i = blockIdx.x * blockDim.x + threadIdx.x; i < nvec; i += stride) {
        const uint32_t elem = i * 4;
        const float4 v = *reinterpret_cast<const float4*>(B + elem);
        __nv_bfloat162 h01 = __float22bfloat162_rn(make_float2(v.x, v.y));
        __nv_bfloat162 h23 = __float22bfloat162_rn(make_float2(v.z, v.w));
        float2 f01 = __bfloat1622float2(h01);
        float2 f23 = __bfloat1622float2(h23);
        __nv_bfloat162 l01 = __float22bfloat162_rn(make_float2(v.x - f01.x, v.y - f01.y));
        __nv_bfloat162 l23 = __float22bfloat162_rn(make_float2(v.z - f23.x, v.w - f23.y));
        uint2 hu, lu;
        hu.x = reinterpret_cast<uint32_t&>(h01); hu.y = reinterpret_cast<uint32_t&>(h23);
        lu.x = reinterpret_cast<uint32_t&>(l01); lu.y = reinterpret_cast<uint32_t&>(l23);
        *reinterpret_cast<uint2*>(&g_Bh[elem]) = hu;
        *reinterpret_cast<uint2*>(&g_Bl[elem]) = lu;
    }
}

// ======================= fused GEMM =======================
// SMEM per CTA (~97KB -> 2 CTAs/SM):
//   [0] tmem ptr; [16],[24] mbarriers
//   stage s at 1024 + s*49152: AH +0 (8KB) AL +8192 BH +16384 (16KB) BL +32768
#define SM_TMEM 0
#define SM_MBAR0 16
#define SM_MBAR1 24
#define OFF_STAGE 1024
#define STAGE_BYTES 49152
#define OFF_AH 0
#define OFF_AL 8192
#define OFF_BH 16384
#define OFF_BL 32768
#define SMEM_TOTAL (1024 + 2 * STAGE_BYTES)   // 99328
#define TMEM_COLS 256

#if !TC_FALLBACK
// LDG chunk c of A into registers (4 x float4 per thread)
__device__ __forceinline__ void loadA_regs(float4 (&r)[4], const float* __restrict__ Ab,
                                           int c, int tid) {
    const float* Ac = Ab + c * BK;
    #pragma unroll
    for (int i = 0; i < 4; i++) {
        const uint32_t idx = (uint32_t)(tid + i * NTHR);   // 0..1023
        const uint32_t row = idx >> 3, j = idx & 7;        // 128 rows x 8 float4
        r[i] = *reinterpret_cast<const float4*>(Ac + (size_t)row * K_ + j * 4);
    }
}

// split registers -> Ah/Al[stage] smem (SW64)
__device__ __forceinline__ void convA_regs(const float4 (&r)[4], uint32_t stg, int tid) {
    const uint32_t ah = stg + OFF_AH;
    const uint32_t al = stg + OFF_AL;
    #pragma unroll
    for (int i = 0; i < 4; i++) {
        const float4 v = r[i];
        __nv_bfloat162 h01 = __float22bfloat162_rn(make_float2(v.x, v.y));
        __nv_bfloat162 h23 = __float22bfloat162_rn(make_float2(v.z, v.w));
        float2 f01 = __bfloat1622float2(h01);
        float2 f23 = __bfloat1622float2(h23);
        __nv_bfloat162 l01 = __float22bfloat162_rn(make_float2(v.x - f01.x, v.y - f01.y));
        __nv_bfloat162 l23 = __float22bfloat162_rn(make_float2(v.z - f23.x, v.w - f23.y));
        const uint32_t idx = (uint32_t)(tid + i * NTHR);
        const uint32_t row = idx >> 3, j = idx & 7;
        const uint32_t off = row * 64u + j * 8u;           // 4 bf16 = 8 bytes
        const uint32_t sw = sw64(off);
        asm volatile("st.shared.v2.b32 [%0], {%1,%2};"
                     :: "r"(ah + sw), "r"(reinterpret_cast<const uint32_t&>(h01)),
                        "r"(reinterpret_cast<const uint32_t&>(h23)) : "memory");
        asm volatile("st.shared.v2.b32 [%0], {%1,%2};"
                     :: "r"(al + sw), "r"(reinterpret_cast<const uint32_t&>(l01)),
                        "r"(reinterpret_cast<const uint32_t&>(l23)) : "memory");
    }
}

// cp.async chunk c of Bh/Bl into stage
__device__ __forceinline__ void loadB_chunk(uint32_t stg, int c,
                                            const __nv_bfloat16* __restrict__ Bhb,
                                            const __nv_bfloat16* __restrict__ Blb,
                                            int tid) {
    const uint32_t bh = stg + OFF_BH;
    const uint32_t bl = stg + OFF_BL;
    const __nv_bfloat16* Bhc = Bhb + c * BK;
    const __nv_bfloat16* Blc = Blb + c * BK;
    #pragma unroll
    for (int i = 0; i < 4; i++) {
        const uint32_t idx = (uint32_t)(tid + i * NTHR);   // 0..1023
        const uint32_t row = idx >> 2, j = idx & 3;        // 256 rows x 4 x 16B
        const uint32_t off = row * 64u + j * 16u;
        const uint32_t sw = sw64(off);
        cp16(bh + sw, Bhc + (size_t)row * K_ + j * 8);
        cp16(bl + sw, Blc + (size_t)row * K_ + j * 8);
    }
}
#endif // !TC_FALLBACK

__global__ void __launch_bounds__(NTHR, 2)
grouped_gemm_tc(const float* __restrict__ A, const int* __restrict__ ent,
                float* __restrict__ C) {
    const int e  = blockIdx.z;
    const int m0 = blockIdx.y * BM;
    const int n0 = blockIdx.x * BN;
    const int nt = __ldg(&ent[e]);
    const int tid = threadIdx.x;
    const int wid = tid >> 5;
    const int lid = tid & 31;

    float* __restrict__ Ce = C + (size_t)e * M_ * N_;

    // ---- fully-invalid tile: vectorized zero-fill ----
    if (m0 >= nt) {
        const float4 z = make_float4(0.f, 0.f, 0.f, 0.f);
        #pragma unroll 8
        for (int i = tid; i < BM * (BN / 4); i += NTHR) {
            const int r = i >> 6;
            const int c4 = (i & 63) << 2;
            *reinterpret_cast<float4*>(&Ce[(size_t)(m0 + r) * N_ + n0 + c4]) = z;
        }
        return;
    }

#if TC_FALLBACK
    // ---- portable-PTX fallback (never executed on GB300) ----
    const __nv_bfloat16* Bh = g_Bh + ((size_t)e * N_ + n0) * K_;
    const __nv_bfloat16* Bl = g_Bl + ((size_t)e * N_ + n0) * K_;
    const float* Ae = A + ((size_t)e * M_ + m0) * K_;
    for (int r = tid; r < BM; r += NTHR) {
        const int m = m0 + r;
        const bool valid = m < nt;
        for (int n = 0; n < BN; n++) {
            float acc = 0.f;
            if (valid) {
                for (int k = 0; k < K_; k++) {
                    float b = __bfloat162float(Bh[(size_t)n * K_ + k]) +
                              __bfloat162float(Bl[(size_t)n * K_ + k]);
                    acc = fmaf(Ae[(size_t)r * K_ + k], b, acc);
                }
            }
            Ce[(size_t)m * N_ + n0 + n] = acc;
        }
    }
#else
    extern __shared__ char smem[];
    const uint32_t sb = smem_u32(smem);

    if (tid == 0) {
        MBAR_INIT(sb + SM_MBAR0, 1);
        MBAR_INIT(sb + SM_MBAR1, 1);
    }
    if (wid == 0) {
        TC_ALLOC(sb + SM_TMEM, TMEM_COLS);
        TC_RELINQ();   // release the alloc permit NOW so a co-resident CTA can alloc
    }
    __syncthreads();
    uint32_t tmem;
    asm volatile("ld.shared.b32 %0, [%1];" : "=r"(tmem) : "r"(sb + SM_TMEM));

    const float* Ab = A + ((size_t)e * M_ + m0) * K_;
    const __nv_bfloat16* Bhb = g_Bh + ((size_t)e * N_ + n0) * K_;
    const __nv_bfloat16* Blb = g_Bl + ((size_t)e * N_ + n0) * K_;

    float4 ar0[4], ar1[4];   // double-buffered A registers

    // prologue: chunk 0 -> stage 0
    loadA_regs(ar0, Ab, 0, tid);
    loadB_chunk(sb + OFF_STAGE, 0, Bhb, Blb, tid);
    CP_COMMIT();

    int wcnt0 = 0, wcnt1 = 0;

    #pragma unroll 1
    for (int c = 0; c < NCHUNK; c++) {
        const int buf = c & 1;
        const uint32_t stg = sb + OFF_STAGE + (uint32_t)buf * STAGE_BYTES;
        if (c + 1 < NCHUNK) {
            const int nb = (c + 1) & 1;
            // A LDG first: regs don't alias smem, overlaps the mbar wait below
            if (nb == 0) loadA_regs(ar0, Ab, c + 1, tid);
            else         loadA_regs(ar1, Ab, c + 1, tid);
            // stage nb last read by MMA chunk c-1 -> wait it before overwrite
            if (c >= 1) {
                if (((c - 1) & 1) == 0) { mbar_wait(sb + SM_MBAR0, wcnt0 & 1); wcnt0++; }
                else                    { mbar_wait(sb + SM_MBAR1, wcnt1 & 1); wcnt1++; }
            }
            loadB_chunk(sb + OFF_STAGE + (uint32_t)nb * STAGE_BYTES, c + 1, Bhb, Blb, tid);
            CP_COMMIT();
            CP_WAIT1();     // chunk c's B arrived (chunk c+1 still in flight)
        } else {
            CP_WAIT0();
        }

        // convert A chunk c into stage buf (freed by MMA c-2 wait above)
        if (buf == 0) convA_regs(ar0, stg, tid);
        else          convA_regs(ar1, stg, tid);

        __syncthreads();
        FENCE_ASYNC();

        if (wid == 0 && elect_one()) {
            const uint64_t dAh = sdesc64(stg + OFF_AH);
            const uint64_t dAl = sdesc64(stg + OFF_AL);
            const uint64_t dBh = sdesc64(stg + OFF_BH);
            const uint64_t dBl = sdesc64(stg + OFF_BL);
            #pragma unroll
            for (int ks = 0; ks < 2; ks++) {        // 2 x K=16 per 32-chunk
                const uint64_t o = (uint64_t)(ks * 2);
                mma_f16_ss(tmem, dAh + o, dBh + o, IDESC, (c == 0 && ks == 0) ? 0u : 1u);
                mma_f16_ss(tmem, dAh + o, dBl + o, IDESC, 1u);
                mma_f16_ss(tmem, dAl + o, dBh + o, IDESC, 1u);
            }
            TC_COMMIT(sb + (buf ? SM_MBAR1 : SM_MBAR0));
        }
        __syncthreads();
    }

    // final chunk (15) committed to mbar1 — in-order completion covers all MMAs
    mbar_wait(sb + SM_MBAR1, wcnt1 & 1);
    TC_FENCE_AFTER();

    // epilogue: warps 0-3 read D (TMEM cols 0..255), mask invalid rows
    if (wid < 4) {
        const int m = m0 + wid * 32 + lid;
        const bool valid = m < nt;
        float* crow = Ce + (size_t)m * N_ + n0;
        const float4 z = make_float4(0.f, 0.f, 0.f, 0.f);
        #pragma unroll
        for (int cb = 0; cb < BN; cb += 32) {
            uint32_t r[32];
            LDTM_X32(r, tmem + cb);
            TC_WAIT_LD();
            #pragma unroll
            for (int j = 0; j < 8; j++) {
                float4 v;
                if (valid) {
                    v = make_float4(__uint_as_float(r[j * 4 + 0]), __uint_as_float(r[j * 4 + 1]),
                                    __uint_as_float(r[j * 4 + 2]), __uint_as_float(r[j * 4 + 3]));
                } else {
                    v = z;
                }
                *reinterpret_cast<float4*>(crow + cb + j * 4) = v;
            }
        }
    }

    __syncthreads();
    if (tid == 0) { MBAR_INVAL(sb + SM_MBAR0); MBAR_INVAL(sb + SM_MBAR1); }
    __syncthreads();
    if (wid == 0) {
        TC_DEALLOC(tmem, TMEM_COLS);
    }
#endif
}

// ======================= launch =======================
extern "C" void kernel_launch(void* const* d_in, const int* in_sizes, int n_in,
                              void* d_out, int out_size)
{
    const float* A   = (const float*)d_in[0];   // [E, M, K]
    const float* B   = (const float*)d_in[1];   // [E, N, K]
    const int*   ent = (const int*)d_in[2];     // [E]
    float*       C   = (float*)d_out;           // [E, M, N]

    convertB<<<1024, 256>>>(B);

    cudaFuncSetAttribute(grouped_gemm_tc,
                         cudaFuncAttributeMaxDynamicSharedMemorySize, SMEM_TOTAL);
    dim3 grid(N_ / BN, M_ / BM, E_);   // (2, 8, 32)
    grouped_gemm_tc<<<grid, NTHR, SMEM_TOTAL>>>(A, ent, C);
}